// round 13
// baseline (speedup 1.0000x reference)
#include <cuda_runtime.h>
#include <cuda_bf16.h>
#include <cstdint>

#define INC    64
#define OUTC   64
#define KOFF   27
#define TP     256
#define NMAX   400000
#define BN_EPS 1e-5f

__device__ int   g_counts[KOFF];
__device__ float g_sum[OUTC];
__device__ float g_sumsq[OUTC];

// precomputed bf16 hi/lo operands
__device__ uint4 FHI4[NMAX * 8];            // feats hi: [row][128B]
__device__ uint4 FLO4[NMAX * 8];            // feats lo
__device__ uint4 WHI4[KOFF * 512];          // W^T hi, SW128-swizzled B tiles (8KB each)
__device__ uint4 WLO4[KOFF * 512];

// ---------------- smem layout ----------------
#define SM_AHI   0
#define SM_ALO   32768
#define SM_BHI   65536
#define SM_BLO   73728
#define SM_DL    81920
#define SMEM_TOTAL (81920 + TP * 4)

#define SWZ128(x) ((x) ^ (((x) >> 3) & 0x70))

static __device__ __forceinline__ uint32_t smem_u32(const void* p) {
    uint32_t a;
    asm("{ .reg .u64 t; cvta.to.shared.u64 t, %1; cvt.u32.u64 %0, t; }" : "=r"(a) : "l"(p));
    return a;
}
static __device__ __forceinline__ void cpasync16(uint32_t dst, const void* src) {
    asm volatile("cp.async.cg.shared.global [%0], [%1], 16;" :: "r"(dst), "l"(src) : "memory");
}
static __device__ __forceinline__ void ldsm4(uint32_t* r, uint32_t addr) {
    asm volatile("ldmatrix.sync.aligned.m8n8.x4.shared.b16 {%0,%1,%2,%3}, [%4];"
                 : "=r"(r[0]), "=r"(r[1]), "=r"(r[2]), "=r"(r[3]) : "r"(addr));
}
static __device__ __forceinline__ void mma_bf16(float* c, const uint32_t* a,
                                                uint32_t b0, uint32_t b1) {
    asm volatile("mma.sync.aligned.m16n8k16.row.col.f32.bf16.bf16.f32 "
                 "{%0,%1,%2,%3}, {%4,%5,%6,%7}, {%8,%9}, {%0,%1,%2,%3};"
                 : "+f"(c[0]), "+f"(c[1]), "+f"(c[2]), "+f"(c[3])
                 : "r"(a[0]), "r"(a[1]), "r"(a[2]), "r"(a[3]), "r"(b0), "r"(b1));
}
static __device__ __forceinline__ void split_bf16(float x, unsigned short& h, unsigned short& l) {
    __nv_bfloat16 hb = __float2bfloat16_rn(x);
    float r = x - __bfloat162float(hb);
    __nv_bfloat16 lb = __float2bfloat16_rn(r);
    h = __bfloat16_as_ushort(hb);
    l = __bfloat16_as_ushort(lb);
}

// ---------- K0: counts + zero BN stats + zero output + feats hi/lo split ----------
__global__ void k_prep(const float* __restrict__ mask, float4* __restrict__ out,
                       const float4* __restrict__ feats4, int n, int total4) {
    const int tid = threadIdx.x;
    if (blockIdx.x == 0) {
        if (tid < OUTC) { g_sum[tid] = 0.f; g_sumsq[tid] = 0.f; }
        if (tid < KOFF) {
            const float* m = mask + (size_t)tid * n;
            int lo = 0, hi = n;
            while (lo < hi) {
                int mid = (lo + hi) >> 1;
                if (m[mid] > 0.5f) lo = mid + 1; else hi = mid;
            }
            g_counts[tid] = lo;
        }
    }
    const int gstride = gridDim.x * blockDim.x;
    for (int i = blockIdx.x * blockDim.x + tid; i < total4; i += gstride)
        out[i] = make_float4(0.f, 0.f, 0.f, 0.f);

    uint2* fh = (uint2*)FHI4;
    uint2* fl = (uint2*)FLO4;
    const int nf4 = n * 16;
    for (int i = blockIdx.x * blockDim.x + tid; i < nf4; i += gstride) {
        float4 v = feats4[i];
        unsigned short h0, h1, h2, h3, l0, l1, l2, l3;
        split_bf16(v.x, h0, l0); split_bf16(v.y, h1, l1);
        split_bf16(v.z, h2, l2); split_bf16(v.w, h3, l3);
        fh[i] = make_uint2((uint32_t)h0 | ((uint32_t)h1 << 16),
                           (uint32_t)h2 | ((uint32_t)h3 << 16));
        fl[i] = make_uint2((uint32_t)l0 | ((uint32_t)l1 << 16),
                           (uint32_t)l2 | ((uint32_t)l3 << 16));
    }
}

// ---------- K0c: W -> transposed, hi/lo, SW128-swizzled B tiles ----------
__global__ void k_conv_w(const float* __restrict__ W) {
    const int k   = blockIdx.x;
    const int tid = threadIdx.x;
    const int c   = tid >> 2;
    const int kq  = (tid & 3) * 16;
    const float* Wk = W + (size_t)k * INC * OUTC;
    char* wh = (char*)(WHI4 + k * 512);
    char* wl = (char*)(WLO4 + k * 512);
    #pragma unroll
    for (int j0 = 0; j0 < 16; j0 += 4) {
        float x0 = Wk[(size_t)(kq + j0 + 0) * OUTC + c];
        float x1 = Wk[(size_t)(kq + j0 + 1) * OUTC + c];
        float x2 = Wk[(size_t)(kq + j0 + 2) * OUTC + c];
        float x3 = Wk[(size_t)(kq + j0 + 3) * OUTC + c];
        unsigned short h0, h1, h2, h3, l0, l1, l2, l3;
        split_bf16(x0, h0, l0); split_bf16(x1, h1, l1);
        split_bf16(x2, h2, l2); split_bf16(x3, h3, l3);
        uint32_t off = SWZ128((uint32_t)(c * 128 + (kq + j0) * 2));
        *(uint2*)(wh + off) = make_uint2((uint32_t)h0 | ((uint32_t)h1 << 16),
                                         (uint32_t)h2 | ((uint32_t)h3 << 16));
        *(uint2*)(wl + off) = make_uint2((uint32_t)l0 | ((uint32_t)l1 << 16),
                                         (uint32_t)l2 | ((uint32_t)l3 << 16));
    }
}

// ---------- K1: HMMA scatter GEMM (shfl-combined red.v4 scatter) ----------
__global__ __launch_bounds__(128)
void k_gemm(const int* __restrict__ in_idx, const int* __restrict__ out_idx,
            float* __restrict__ out, int n)
{
    extern __shared__ char smem[];
    const int k    = blockIdx.y;
    const int base = blockIdx.x * TP;
    const int cnt  = g_counts[k];
    if (base >= cnt) return;
    const int np = min(TP, cnt - base);

    const uint32_t sb = smem_u32(smem);
    const int tid = threadIdx.x, wid = tid >> 5, lane = tid & 31;
    const size_t kbase = (size_t)k * n + base;
    int* dl = (int*)(smem + SM_DL);

    // --- B tiles via cp.async (8KB hi + 8KB lo, pre-swizzled) ---
    {
        const uint4* wh = WHI4 + k * 512;
        const uint4* wl = WLO4 + k * 512;
        #pragma unroll
        for (int j = 0; j < 4; j++) {
            cpasync16(sb + SM_BHI + (tid + j * 128) * 16, wh + tid + j * 128);
            cpasync16(sb + SM_BLO + (tid + j * 128) * 16, wl + tid + j * 128);
        }
    }

    // --- gather A via cp.async: 2 pairs/thread; rows >= np stay garbage ---
    {
        #pragma unroll
        for (int g = 0; g < 2; g++) {
            const int p = tid + g * 128;
            if (p < np) {
                const int src = in_idx[kbase + p];
                dl[p] = out_idx[kbase + p];
                const uint4* fh = FHI4 + (size_t)src * 8;
                const uint4* fl = FLO4 + (size_t)src * 8;
                #pragma unroll
                for (int j = 0; j < 8; j++) {
                    uint32_t off = SWZ128((uint32_t)(p * 128 + j * 16));
                    cpasync16(sb + SM_AHI + off, fh + j);
                    cpasync16(sb + SM_ALO + off, fl + j);
                }
            }
        }
    }
    asm volatile("cp.async.commit_group;" ::: "memory");
    asm volatile("cp.async.wait_group 0;" ::: "memory");
    __syncthreads();

    // --- compute: warp = 64 pairs x 64 cols; 3-pass hi/lo mma.sync ---
    const int pm = wid * 64;
    float acc[4][8][4];
    #pragma unroll
    for (int mb = 0; mb < 4; mb++)
        #pragma unroll
        for (int i = 0; i < 8; i++)
            #pragma unroll
            for (int j = 0; j < 4; j++) acc[mb][i][j] = 0.f;

    const int lm = lane >> 3;
    const int lr = lane & 7;

    #pragma unroll
    for (int ks = 0; ks < 4; ks++) {
        uint32_t ah[4][4], al[4][4];
        #pragma unroll
        for (int mb = 0; mb < 4; mb++) {
            const int arow = pm + mb * 16 + lr + (lm & 1) * 8;
            const int acol = ks * 16 + (lm >> 1) * 8;
            const uint32_t aoff = SWZ128((uint32_t)(arow * 128 + acol * 2));
            ldsm4(ah[mb], sb + SM_AHI + aoff);
            ldsm4(al[mb], sb + SM_ALO + aoff);
        }
        #pragma unroll
        for (int nn = 0; nn < 4; nn++) {
            const int brow = nn * 16 + lr + (lm >> 1) * 8;
            const int bcol = ks * 16 + (lm & 1) * 8;
            const uint32_t boff = SWZ128((uint32_t)(brow * 128 + bcol * 2));
            uint32_t bh[4], bl[4];
            ldsm4(bh, sb + SM_BHI + boff);
            ldsm4(bl, sb + SM_BLO + boff);
            #pragma unroll
            for (int mb = 0; mb < 4; mb++) {
                mma_bf16(acc[mb][2 * nn + 0], ah[mb], bh[0], bh[1]);
                mma_bf16(acc[mb][2 * nn + 1], ah[mb], bh[2], bh[3]);
                mma_bf16(acc[mb][2 * nn + 0], al[mb], bh[0], bh[1]);
                mma_bf16(acc[mb][2 * nn + 1], al[mb], bh[2], bh[3]);
                mma_bf16(acc[mb][2 * nn + 0], ah[mb], bl[0], bl[1]);
                mma_bf16(acc[mb][2 * nn + 1], ah[mb], bl[2], bl[3]);
            }
        }
    }

    // --- scatter: shfl-combine lane pairs (same row, adjacent col pairs) -> red.v4 ---
    // lane l and l^1 share row = lane>>2; l holds cols (l&3)*2..+1.
    // Even member assembles 4 contiguous cols and issues one red.v4.
    {
        const int colq = (lane & 2) * 2;          // 0 or 4 within the 8-col group
        const bool evn = (lane & 1) == 0;
        #pragma unroll
        for (int mb = 0; mb < 4; mb++) {
            const int r0 = pm + mb * 16 + (lane >> 2);
            #pragma unroll
            for (int half = 0; half < 2; half++) {
                const int r = r0 + half * 8;
                const bool act = (r < np);
                float* o = act ? (out + (size_t)dl[r] * OUTC) : out;
                #pragma unroll
                for (int j = 0; j < 8; j++) {
                    float a0 = acc[mb][j][2 * half];
                    float a1 = acc[mb][j][2 * half + 1];
                    float p0 = __shfl_xor_sync(0xFFFFFFFF, a0, 1);
                    float p1 = __shfl_xor_sync(0xFFFFFFFF, a1, 1);
                    if (evn && act) {
                        const int col = (j >> 1) * 16 + (j & 1) * 8 + colq;
                        asm volatile("red.global.add.v4.f32 [%0], {%1,%2,%3,%4};"
                                     :: "l"(o + col), "f"(a0), "f"(a1), "f"(p0), "f"(p1)
                                     : "memory");
                    }
                }
            }
        }
    }
}

// ---------- K2: per-channel sum / sumsq ----------
__global__ __launch_bounds__(256)
void k_stats(const float4* __restrict__ out4, int total4) {
    const int tid = threadIdx.x;
    const int cg  = (tid & 15) * 4;
    float s0 = 0.f, s1 = 0.f, s2 = 0.f, s3 = 0.f;
    float q0 = 0.f, q1 = 0.f, q2 = 0.f, q3 = 0.f;
    const int stride = gridDim.x * 256;
    int i = blockIdx.x * 256 + tid;
    for (; i + 3 * stride < total4; i += 4 * stride) {
        float4 v0 = out4[i];
        float4 v1 = out4[i + stride];
        float4 v2 = out4[i + 2 * stride];
        float4 v3 = out4[i + 3 * stride];
        s0 += v0.x + v1.x + v2.x + v3.x;
        s1 += v0.y + v1.y + v2.y + v3.y;
        s2 += v0.z + v1.z + v2.z + v3.z;
        s3 += v0.w + v1.w + v2.w + v3.w;
        q0 += v0.x*v0.x + v1.x*v1.x + v2.x*v2.x + v3.x*v3.x;
        q1 += v0.y*v0.y + v1.y*v1.y + v2.y*v2.y + v3.y*v3.y;
        q2 += v0.z*v0.z + v1.z*v1.z + v2.z*v2.z + v3.z*v3.z;
        q3 += v0.w*v0.w + v1.w*v1.w + v2.w*v2.w + v3.w*v3.w;
    }
    for (; i < total4; i += stride) {
        float4 v = out4[i];
        s0 += v.x; s1 += v.y; s2 += v.z; s3 += v.w;
        q0 += v.x*v.x; q1 += v.y*v.y; q2 += v.z*v.z; q3 += v.w*v.w;
    }
    __shared__ float ssum[OUTC];
    __shared__ float ssq[OUTC];
    if (tid < OUTC) { ssum[tid] = 0.f; ssq[tid] = 0.f; }
    __syncthreads();
    atomicAdd(&ssum[cg + 0], s0); atomicAdd(&ssq[cg + 0], q0);
    atomicAdd(&ssum[cg + 1], s1); atomicAdd(&ssq[cg + 1], q1);
    atomicAdd(&ssum[cg + 2], s2); atomicAdd(&ssq[cg + 2], q2);
    atomicAdd(&ssum[cg + 3], s3); atomicAdd(&ssq[cg + 3], q3);
    __syncthreads();
    if (tid < OUTC) {
        atomicAdd(&g_sum[tid],   ssum[tid]);
        atomicAdd(&g_sumsq[tid], ssq[tid]);
    }
}

// ---------- K3: BatchNorm + ReLU ----------
__global__ __launch_bounds__(256)
void k_bn(float4* __restrict__ out,
          const float* __restrict__ gamma, const float* __restrict__ beta,
          int total4, float invN)
{
    const int tid = threadIdx.x;
    const int cg  = (tid & 15) * 4;
    float mean[4], scl[4], bet[4];
    #pragma unroll
    for (int j = 0; j < 4; j++) {
        int c = cg + j;
        float m = g_sum[c] * invN;
        float var = g_sumsq[c] * invN - m * m;
        mean[j] = m;
        scl[j] = rsqrtf(var + BN_EPS) * gamma[c];
        bet[j] = beta[c];
    }
    const int stride = gridDim.x * 256;
    for (int i = blockIdx.x * 256 + tid; i < total4; i += stride) {
        float4 v = out[i];
        v.x = fmaxf((v.x - mean[0]) * scl[0] + bet[0], 0.f);
        v.y = fmaxf((v.y - mean[1]) * scl[1] + bet[1], 0.f);
        v.z = fmaxf((v.z - mean[2]) * scl[2] + bet[2], 0.f);
        v.w = fmaxf((v.w - mean[3]) * scl[3] + bet[3], 0.f);
        out[i] = v;
    }
}

// ---------- launch ----------
extern "C" void kernel_launch(void* const* d_in, const int* in_sizes, int n_in,
                              void* d_out, int out_size)
{
    const float* feats   = (const float*)d_in[0];
    const float* W       = (const float*)d_in[1];
    const float* gamma   = (const float*)d_in[2];
    const float* beta    = (const float*)d_in[3];
    const float* mask    = (const float*)d_in[4];
    const int*   in_idx  = (const int*)d_in[5];
    const int*   out_idx = (const int*)d_in[6];
    float*       out     = (float*)d_out;

    const int n = in_sizes[0] / INC;
    const int total4 = (n * OUTC) / 4;

    cudaFuncSetAttribute(k_gemm, cudaFuncAttributeMaxDynamicSharedMemorySize, SMEM_TOTAL);

    k_prep<<<2048, 256>>>(mask, (float4*)out, (const float4*)feats, n, total4);
    k_conv_w<<<KOFF, 256>>>(W);

    dim3 grid((n + TP - 1) / TP, KOFF);
    k_gemm<<<grid, 128, SMEM_TOTAL>>>(in_idx, out_idx, out, n);

    k_stats<<<1184, 256>>>((const float4*)out, total4);
    k_bn<<<2048, 256>>>((float4*)out, gamma, beta, total4, 1.0f / (float)n);
}